// round 11
// baseline (speedup 1.0000x reference)
#include <cuda_runtime.h>
#include <cstdint>

#define BN 64
#define BD 512
#define BB 16

// ---------------------------------------------------------------------------
// Compile-time structure table.
// ---------------------------------------------------------------------------
struct TblT { int v[4096]; };

constexpr int ilog2c(int v) { int l = 0; while ((1 << (l + 1)) <= v) l++; return l; }

constexpr int pack_entry_c(int a, int b) {
    int len = b - a;
    int l = ilog2c(len);
    const int off[7] = {0, 64, 127, 188, 245, 294, 327};
    int i1 = off[l] + a;
    int i2 = off[l] + b - (1 << l);
    return i1 | (i2 << 10) | 0x40000000;
}

constexpr TblT make_tbl() {
    TblT t{};
    for (int i = 0; i < 4096; i++) t.v[i] = -1;
    int lo[64] = {}, hi[64] = {};
    for (int p = 0; p < 64; p++) {
        lo[p] = p; hi[p] = p + 1;
        t.v[p * 64 + p] = pack_entry_c(p, p + 1);
    }
    int len = 64, stride = 1, offset = 0;
    const int counts[3] = {15, 8, 8};
    for (int ci = 0; ci < 3; ci++) {
        for (int tt = 0; tt < counts[ci]; tt++) {
            offset += stride;
            int k = (ci == 0 || tt > 0) ? 2 : 3;
            int s = (k == 2) ? 1 : 2;
            int nl = (len - k) / s + 1;
            for (int p = 0; p < nl; p++) {
                int a = lo[p * s];
                int b = hi[p * s + k - 1];
                lo[p] = a; hi[p] = b;
                int i = p * stride, j = i + offset;
                t.v[i * 64 + j] = pack_entry_c(a, b);
            }
            len = nl;
        }
        stride *= 2;
    }
    return t;
}

constexpr TblT HOST_TBL = make_tbl();
__device__ const TblT g_tbl = HOST_TBL;

// Scratch (static device globals — no allocations)
__device__ float d_part[2 * BB * 64 * 1024];  // K-split partial sums (no bias)
__device__ float d_factor[BB * 4096];         // 1 + softmax weights

// ---------------------------------------------------------------------------
// Kernel 1: K-split GEMM, 8x4 per-thread tile, COALESCED W loads
// (thread = (row, col-quad): each warp-LDG touches 8 lines, not 32).
// Grid (8 o-tiles, 16 b, 2 ks), 256 threads, double-buffered smem.
// ---------------------------------------------------------------------------
__global__ __launch_bounds__(256) void gemm_kernel(
    const float* __restrict__ x, const float* __restrict__ w_v,
    const float* __restrict__ w_c)
{
    int b  = blockIdx.y;
    int o0 = blockIdx.x * 128;
    int ks = blockIdx.z;
    const float* W = (o0 < 512) ? (w_v + (size_t)o0 * 512)
                                : (w_c + (size_t)(o0 - 512) * 512);
    W += ks * 256;
    const float* xb = x + (size_t)b * BD * BN + (size_t)ks * 256 * 64;

    __shared__ float As[2][16][64];    // [kk][n]
    __shared__ float Ws[2][16][132];   // [kk][o], padded

    int tid = threadIdx.x;
    int tx = tid & 15;        // n-group: 4 n per thread
    int ty = tid >> 4;        // o-group: 8 o per thread
    int wrow = tid >> 2;      // W loader: o row 0..63 (and +64)
    int wc4  = (tid & 3) * 4; // W loader: k-quad within 16-wide tile

    float acc[8][4];
#pragma unroll
    for (int r = 0; r < 8; r++)
#pragma unroll
        for (int c = 0; c < 4; c++) acc[r][c] = 0.f;

    // prologue: tile 0 -> slot 0
    {
        int kk = tid >> 4, n4 = tid & 15;
        *(float4*)&As[0][kk][n4 * 4] = *(const float4*)(xb + (size_t)kk * 64 + n4 * 4);
        float4 va = *(const float4*)(W + (size_t)wrow * 512 + wc4);
        float4 vb = *(const float4*)(W + (size_t)(wrow + 64) * 512 + wc4);
        Ws[0][wc4 + 0][wrow] = va.x; Ws[0][wc4 + 1][wrow] = va.y;
        Ws[0][wc4 + 2][wrow] = va.z; Ws[0][wc4 + 3][wrow] = va.w;
        Ws[0][wc4 + 0][wrow + 64] = vb.x; Ws[0][wc4 + 1][wrow + 64] = vb.y;
        Ws[0][wc4 + 2][wrow + 64] = vb.z; Ws[0][wc4 + 3][wrow + 64] = vb.w;
    }
    __syncthreads();

    for (int t = 0; t < 16; t++) {
        int s = t & 1, ns = s ^ 1;
        if (t < 15) {
            int kb = (t + 1) * 16;
            int kk = tid >> 4, n4 = tid & 15;
            *(float4*)&As[ns][kk][n4 * 4] =
                *(const float4*)(xb + (size_t)(kb + kk) * 64 + n4 * 4);
            float4 va = *(const float4*)(W + (size_t)wrow * 512 + kb + wc4);
            float4 vb = *(const float4*)(W + (size_t)(wrow + 64) * 512 + kb + wc4);
            Ws[ns][wc4 + 0][wrow] = va.x; Ws[ns][wc4 + 1][wrow] = va.y;
            Ws[ns][wc4 + 2][wrow] = va.z; Ws[ns][wc4 + 3][wrow] = va.w;
            Ws[ns][wc4 + 0][wrow + 64] = vb.x; Ws[ns][wc4 + 1][wrow + 64] = vb.y;
            Ws[ns][wc4 + 2][wrow + 64] = vb.z; Ws[ns][wc4 + 3][wrow + 64] = vb.w;
        }
#pragma unroll
        for (int kk = 0; kk < 16; kk++) {
            float4 n4 = *(const float4*)&As[s][kk][tx * 4];
            float4 o40 = *(const float4*)&Ws[s][kk][ty * 8];
            float4 o41 = *(const float4*)&Ws[s][kk][ty * 8 + 4];
            float nv[4] = {n4.x, n4.y, n4.z, n4.w};
            float ov[8] = {o40.x, o40.y, o40.z, o40.w, o41.x, o41.y, o41.z, o41.w};
#pragma unroll
            for (int r = 0; r < 8; r++)
#pragma unroll
                for (int c = 0; c < 4; c++)
                    acc[r][c] += ov[r] * nv[c];
        }
        __syncthreads();
    }

    float* dst = d_part + ((size_t)ks * BB + b) * 65536;
#pragma unroll
    for (int c = 0; c < 4; c++) {
        int n = tx * 4 + c;
        float4 lo = make_float4(acc[0][c], acc[1][c], acc[2][c], acc[3][c]);
        float4 hi = make_float4(acc[4][c], acc[5][c], acc[6][c], acc[7][c]);
        *(float4*)&dst[(size_t)n * 1024 + o0 + ty * 8]     = lo;
        *(float4*)&dst[(size_t)n * 1024 + o0 + ty * 8 + 4] = hi;
    }
}

// ---------------------------------------------------------------------------
// Kernel 2: combine partials + bias; m2m = m_k @ m_q^T / 8, warp-shuffle
// row softmax, factor = 1 + w. 8-row tiles -> grid (8,16) = 128 blocks.
// Thread layout: tr = warp (row), tc = lane; 2 cols per thread.
// ---------------------------------------------------------------------------
__global__ __launch_bounds__(256) void attn_kernel(
    const float* __restrict__ b_v, const float* __restrict__ b_c)
{
    int b = blockIdx.y;
    int n0 = blockIdx.x * 8;
    __shared__ float Sk[8][33];
    __shared__ float Sq[32][68];
    int tid = threadIdx.x;
    int tr = tid >> 5;        // row within tile (= warp id)
    int tc = tid & 31;        // lane = column
    float acc0 = 0.f, acc1 = 0.f;
    const float* P0 = d_part + (size_t)b * 65536;
    const float* P1 = d_part + (size_t)(BB + b) * 65536;

    for (int kt = 0; kt < 512; kt += 32) {
        {
            size_t off = (size_t)(n0 + tr) * 1024 + kt + tc;
            Sk[tr][tc] = P0[off] + P1[off] + b_v[kt + tc];
        }
#pragma unroll
        for (int it = 0; it < 2; it++) {
            int u = tid + it * 256;
            int m = u >> 3, c4 = u & 7;
            size_t off = (size_t)m * 1024 + 512 + kt + c4 * 4;
            float4 v0 = *(const float4*)(P0 + off);
            float4 v1 = *(const float4*)(P1 + off);
            float4 vb = *(const float4*)(b_c + kt + c4 * 4);
            Sq[c4 * 4 + 0][m] = v0.x + v1.x + vb.x;
            Sq[c4 * 4 + 1][m] = v0.y + v1.y + vb.y;
            Sq[c4 * 4 + 2][m] = v0.z + v1.z + vb.z;
            Sq[c4 * 4 + 3][m] = v0.w + v1.w + vb.w;
        }
        __syncthreads();
#pragma unroll
        for (int kk = 0; kk < 32; kk++) {
            float a = Sk[tr][kk];
            acc0 += a * Sq[kk][tc];
            acc1 += a * Sq[kk][tc + 32];
        }
        __syncthreads();
    }

    float s0 = acc0 * 0.125f, s1 = acc1 * 0.125f;
    float mx = fmaxf(s0, s1);
#pragma unroll
    for (int o = 16; o; o >>= 1) mx = fmaxf(mx, __shfl_xor_sync(0xFFFFFFFFu, mx, o));
    float e0 = __expf(s0 - mx), e1 = __expf(s1 - mx);
    float sum = e0 + e1;
#pragma unroll
    for (int o = 16; o; o >>= 1) sum += __shfl_xor_sync(0xFFFFFFFFu, sum, o);
    float inv = 1.f / sum;
    float* fp = d_factor + (size_t)b * 4096 + (size_t)(n0 + tr) * 64;
    fp[tc]      = 1.f + e0 * inv;
    fp[tc + 32] = 1.f + e1 * inv;
}

// ---------------------------------------------------------------------------
// Kernel 3: PERSISTENT main kernel. 888 CTAs (6/SM), each processes ~9 rows.
// 3-slot rolling TMA pipeline across rows: wait_group.read 2 only when a slot
// is reused; single read-0 drain per CTA at exit. Dynamic smem: 36 KB.
// ---------------------------------------------------------------------------
#define MAIN_CTAS 888
#define SMEM_MAIN_BYTES (3 * 3 * 1024 * 4)

__global__ __launch_bounds__(256) void main_kernel(
    const float* __restrict__ x, float* __restrict__ out)
{
    __shared__ float lev[352];
    extern __shared__ float smb[];   // [3][3][1024]

    int tid = threadIdx.x;
    const size_t mapsz = (size_t)BB * BD * 4096;
    const int4* tblv = (const int4*)g_tbl.v;
    const int offA[7] = {0, 64, 127, 188, 245, 294, 327};

    int cc = 0;   // global chunk counter (slot = cc % 3)
    for (int row = blockIdx.x; row < BB * BD; row += MAIN_CTAS) {
        int b = row >> 9;
        int d = row & 511;

        // Build the 7-level sparse max table for this row.
        if (tid < 64) lev[tid] = x[(size_t)row * 64 + tid];
        __syncthreads();
#pragma unroll
        for (int l = 1; l < 7; l++) {
            int cnt = 65 - (1 << l);
            int half = 1 << (l - 1);
            if (tid < cnt)
                lev[offA[l] + tid] = fmaxf(lev[offA[l - 1] + tid],
                                           lev[offA[l - 1] + tid + half]);
            __syncthreads();
        }

        const float4* facv = (const float4*)(d_factor + (size_t)b * 4096);
        float* maskp = out + 3 * mapsz + (size_t)b * 4096;
        float* gBase = out + (size_t)row * 4096;
        bool wmask = (d == 0);

#pragma unroll
        for (int c = 0; c < 4; c++) {
            int slot = cc % 3;
            float* buf = smb + slot * 3072;
            if (cc >= 3) {
                // Slot was committed 3 groups ago; free when <=2 outstanding.
                if (tid == 0)
                    asm volatile("cp.async.bulk.wait_group.read 2;" ::: "memory");
                __syncthreads();
            }

            int q = c * 256 + tid;
            int4 t4 = tblv[q];
            int i  = q >> 4;
            int j0 = (q & 15) << 2;
            float4* pB = (float4*)buf + tid;
            float4* pL = (float4*)buf + 256 + tid;
            float4* pC = (float4*)buf + 512 + tid;

            if ((t4.x & t4.y & t4.z & t4.w) < 0) {
                float4 z = make_float4(0.f, 0.f, 0.f, 0.f);
                *pB = z; *pL = z; *pC = z;
                if (wmask) __stcs((float4*)maskp + q, z);
            } else {
                float4 f4 = facv[q];
                float fs[4] = {f4.x, f4.y, f4.z, f4.w};
                int   ts[4] = {t4.x, t4.y, t4.z, t4.w};
                float xi = lev[i];
                float bo[4], lc[4], co[4], mk[4];
#pragma unroll
                for (int ccq = 0; ccq < 4; ccq++) {
                    int t = ts[ccq];
                    if (t < 0) { bo[ccq] = 0.f; lc[ccq] = 0.f; co[ccq] = 0.f; mk[ccq] = 0.f; }
                    else {
                        int j = j0 + ccq;
                        float xj = lev[j];
                        float xk = lev[(i + j) >> 1];
                        float f  = fs[ccq];
                        bo[ccq] = (xi + xj) * 0.5f * f;
                        lc[ccq] = (xi + xj + 0.5f * xk) * (1.f / 2.5f) * f;
                        co[ccq] = fmaxf(lev[t & 1023], lev[(t >> 10) & 1023]) * f;
                        mk[ccq] = 1.f;
                    }
                }
                *pB = make_float4(bo[0], bo[1], bo[2], bo[3]);
                *pL = make_float4(lc[0], lc[1], lc[2], lc[3]);
                *pC = make_float4(co[0], co[1], co[2], co[3]);
                if (wmask) __stcs((float4*)maskp + q,
                                  make_float4(mk[0], mk[1], mk[2], mk[3]));
            }
            __syncthreads();

            if (tid == 0) {
                uint32_t s0;
                asm("{ .reg .u64 t; cvta.to.shared.u64 t, %1; cvt.u32.u64 %0, t; }"
                    : "=r"(s0) : "l"(buf));
                asm volatile("fence.proxy.async.shared::cta;" ::: "memory");
                asm volatile("cp.async.bulk.global.shared::cta.bulk_group [%0], [%1], %2;"
                             :: "l"(gBase + c * 1024), "r"(s0), "r"(4096) : "memory");
                asm volatile("cp.async.bulk.global.shared::cta.bulk_group [%0], [%1], %2;"
                             :: "l"(gBase + mapsz + c * 1024), "r"(s0 + 4096), "r"(4096) : "memory");
                asm volatile("cp.async.bulk.global.shared::cta.bulk_group [%0], [%1], %2;"
                             :: "l"(gBase + 2 * mapsz + c * 1024), "r"(s0 + 8192), "r"(4096) : "memory");
                asm volatile("cp.async.bulk.commit_group;" ::: "memory");
            }
            cc++;
        }
    }

    // Single drain per CTA.
    if (tid == 0)
        asm volatile("cp.async.bulk.wait_group.read 0;" ::: "memory");
}

// ---------------------------------------------------------------------------
extern "C" void kernel_launch(void* const* d_in, const int* in_sizes, int n_in,
                              void* d_out, int out_size) {
    const float* x   = (const float*)d_in[0];
    const float* w_c = (const float*)d_in[1];
    const float* b_c = (const float*)d_in[2];
    const float* w_v = (const float*)d_in[3];
    const float* b_v = (const float*)d_in[4];
    float* out = (float*)d_out;

    gemm_kernel<<<dim3(8, 16, 2), 256>>>(x, w_v, w_c);
    attn_kernel<<<dim3(8, 16), 256>>>(b_v, b_c);
    main_kernel<<<MAIN_CTAS, 256, SMEM_MAIN_BYTES>>>(x, out);
}

// round 13
// speedup vs baseline: 1.2192x; 1.2192x over previous
#include <cuda_runtime.h>
#include <cstdint>

#define BN 64
#define BD 512
#define BB 16

// ---------------------------------------------------------------------------
// Compile-time structure table.
// ---------------------------------------------------------------------------
struct TblT { int v[4096]; };

constexpr int ilog2c(int v) { int l = 0; while ((1 << (l + 1)) <= v) l++; return l; }

constexpr int pack_entry_c(int a, int b) {
    int len = b - a;
    int l = ilog2c(len);
    const int off[7] = {0, 64, 127, 188, 245, 294, 327};
    int i1 = off[l] + a;
    int i2 = off[l] + b - (1 << l);
    return i1 | (i2 << 10) | 0x40000000;
}

constexpr TblT make_tbl() {
    TblT t{};
    for (int i = 0; i < 4096; i++) t.v[i] = -1;
    int lo[64] = {}, hi[64] = {};
    for (int p = 0; p < 64; p++) {
        lo[p] = p; hi[p] = p + 1;
        t.v[p * 64 + p] = pack_entry_c(p, p + 1);
    }
    int len = 64, stride = 1, offset = 0;
    const int counts[3] = {15, 8, 8};
    for (int ci = 0; ci < 3; ci++) {
        for (int tt = 0; tt < counts[ci]; tt++) {
            offset += stride;
            int k = (ci == 0 || tt > 0) ? 2 : 3;
            int s = (k == 2) ? 1 : 2;
            int nl = (len - k) / s + 1;
            for (int p = 0; p < nl; p++) {
                int a = lo[p * s];
                int b = hi[p * s + k - 1];
                lo[p] = a; hi[p] = b;
                int i = p * stride, j = i + offset;
                t.v[i * 64 + j] = pack_entry_c(a, b);
            }
            len = nl;
        }
        stride *= 2;
    }
    return t;
}

constexpr TblT HOST_TBL = make_tbl();
__device__ const TblT g_tbl = HOST_TBL;

// Scratch (static device globals — no allocations)
__device__ float d_part[2 * BB * 64 * 1024];  // K-split partial sums (no bias)
__device__ float d_factor[BB * 4096];         // 1 + softmax weights

// ---------------------------------------------------------------------------
// Kernel 1 (R11-proven, 37.9us): K-split GEMM, 8x4 per-thread tile,
// coalesced W loads. Grid (8 o-tiles, 16 b, 2 ks), double-buffered smem.
// ---------------------------------------------------------------------------
__global__ __launch_bounds__(256) void gemm_kernel(
    const float* __restrict__ x, const float* __restrict__ w_v,
    const float* __restrict__ w_c)
{
    int b  = blockIdx.y;
    int o0 = blockIdx.x * 128;
    int ks = blockIdx.z;
    const float* W = (o0 < 512) ? (w_v + (size_t)o0 * 512)
                                : (w_c + (size_t)(o0 - 512) * 512);
    W += ks * 256;
    const float* xb = x + (size_t)b * BD * BN + (size_t)ks * 256 * 64;

    __shared__ float As[2][16][64];    // [kk][n]
    __shared__ float Ws[2][16][132];   // [kk][o], padded

    int tid = threadIdx.x;
    int tx = tid & 15;        // n-group: 4 n per thread
    int ty = tid >> 4;        // o-group: 8 o per thread
    int wrow = tid >> 2;      // W loader: o row 0..63 (and +64)
    int wc4  = (tid & 3) * 4; // W loader: k-quad within 16-wide tile

    float acc[8][4];
#pragma unroll
    for (int r = 0; r < 8; r++)
#pragma unroll
        for (int c = 0; c < 4; c++) acc[r][c] = 0.f;

    // prologue: tile 0 -> slot 0
    {
        int kk = tid >> 4, n4 = tid & 15;
        *(float4*)&As[0][kk][n4 * 4] = *(const float4*)(xb + (size_t)kk * 64 + n4 * 4);
        float4 va = *(const float4*)(W + (size_t)wrow * 512 + wc4);
        float4 vb = *(const float4*)(W + (size_t)(wrow + 64) * 512 + wc4);
        Ws[0][wc4 + 0][wrow] = va.x; Ws[0][wc4 + 1][wrow] = va.y;
        Ws[0][wc4 + 2][wrow] = va.z; Ws[0][wc4 + 3][wrow] = va.w;
        Ws[0][wc4 + 0][wrow + 64] = vb.x; Ws[0][wc4 + 1][wrow + 64] = vb.y;
        Ws[0][wc4 + 2][wrow + 64] = vb.z; Ws[0][wc4 + 3][wrow + 64] = vb.w;
    }
    __syncthreads();

    for (int t = 0; t < 16; t++) {
        int s = t & 1, ns = s ^ 1;
        if (t < 15) {
            int kb = (t + 1) * 16;
            int kk = tid >> 4, n4 = tid & 15;
            *(float4*)&As[ns][kk][n4 * 4] =
                *(const float4*)(xb + (size_t)(kb + kk) * 64 + n4 * 4);
            float4 va = *(const float4*)(W + (size_t)wrow * 512 + kb + wc4);
            float4 vb = *(const float4*)(W + (size_t)(wrow + 64) * 512 + kb + wc4);
            Ws[ns][wc4 + 0][wrow] = va.x; Ws[ns][wc4 + 1][wrow] = va.y;
            Ws[ns][wc4 + 2][wrow] = va.z; Ws[ns][wc4 + 3][wrow] = va.w;
            Ws[ns][wc4 + 0][wrow + 64] = vb.x; Ws[ns][wc4 + 1][wrow + 64] = vb.y;
            Ws[ns][wc4 + 2][wrow + 64] = vb.z; Ws[ns][wc4 + 3][wrow + 64] = vb.w;
        }
#pragma unroll
        for (int kk = 0; kk < 16; kk++) {
            float4 n4 = *(const float4*)&As[s][kk][tx * 4];
            float4 o40 = *(const float4*)&Ws[s][kk][ty * 8];
            float4 o41 = *(const float4*)&Ws[s][kk][ty * 8 + 4];
            float nv[4] = {n4.x, n4.y, n4.z, n4.w};
            float ov[8] = {o40.x, o40.y, o40.z, o40.w, o41.x, o41.y, o41.z, o41.w};
#pragma unroll
            for (int r = 0; r < 8; r++)
#pragma unroll
                for (int c = 0; c < 4; c++)
                    acc[r][c] += ov[r] * nv[c];
        }
        __syncthreads();
    }

    float* dst = d_part + ((size_t)ks * BB + b) * 65536;
#pragma unroll
    for (int c = 0; c < 4; c++) {
        int n = tx * 4 + c;
        float4 lo = make_float4(acc[0][c], acc[1][c], acc[2][c], acc[3][c]);
        float4 hi = make_float4(acc[4][c], acc[5][c], acc[6][c], acc[7][c]);
        *(float4*)&dst[(size_t)n * 1024 + o0 + ty * 8]     = lo;
        *(float4*)&dst[(size_t)n * 1024 + o0 + ty * 8 + 4] = hi;
    }
}

// ---------------------------------------------------------------------------
// Kernel 2 (R11): combine partials + bias; m2m = m_k @ m_q^T / 8,
// warp-shuffle row softmax, factor = 1 + w. Grid (8,16) = 128 blocks.
// ---------------------------------------------------------------------------
__global__ __launch_bounds__(256) void attn_kernel(
    const float* __restrict__ b_v, const float* __restrict__ b_c)
{
    int b = blockIdx.y;
    int n0 = blockIdx.x * 8;
    __shared__ float Sk[8][33];
    __shared__ float Sq[32][68];
    int tid = threadIdx.x;
    int tr = tid >> 5;        // row within tile (= warp id)
    int tc = tid & 31;        // lane = column
    float acc0 = 0.f, acc1 = 0.f;
    const float* P0 = d_part + (size_t)b * 65536;
    const float* P1 = d_part + (size_t)(BB + b) * 65536;

    for (int kt = 0; kt < 512; kt += 32) {
        {
            size_t off = (size_t)(n0 + tr) * 1024 + kt + tc;
            Sk[tr][tc] = P0[off] + P1[off] + b_v[kt + tc];
        }
#pragma unroll
        for (int it = 0; it < 2; it++) {
            int u = tid + it * 256;
            int m = u >> 3, c4 = u & 7;
            size_t off = (size_t)m * 1024 + 512 + kt + c4 * 4;
            float4 v0 = *(const float4*)(P0 + off);
            float4 v1 = *(const float4*)(P1 + off);
            float4 vb = *(const float4*)(b_c + kt + c4 * 4);
            Sq[c4 * 4 + 0][m] = v0.x + v1.x + vb.x;
            Sq[c4 * 4 + 1][m] = v0.y + v1.y + vb.y;
            Sq[c4 * 4 + 2][m] = v0.z + v1.z + vb.z;
            Sq[c4 * 4 + 3][m] = v0.w + v1.w + vb.w;
        }
        __syncthreads();
#pragma unroll
        for (int kk = 0; kk < 32; kk++) {
            float a = Sk[tr][kk];
            acc0 += a * Sq[kk][tc];
            acc1 += a * Sq[kk][tc + 32];
        }
        __syncthreads();
    }

    float s0 = acc0 * 0.125f, s1 = acc1 * 0.125f;
    float mx = fmaxf(s0, s1);
#pragma unroll
    for (int o = 16; o; o >>= 1) mx = fmaxf(mx, __shfl_xor_sync(0xFFFFFFFFu, mx, o));
    float e0 = __expf(s0 - mx), e1 = __expf(s1 - mx);
    float sum = e0 + e1;
#pragma unroll
    for (int o = 16; o; o >>= 1) sum += __shfl_xor_sync(0xFFFFFFFFu, sum, o);
    float inv = 1.f / sum;
    float* fp = d_factor + (size_t)b * 4096 + (size_t)(n0 + tr) * 64;
    fp[tc]      = 1.f + e0 * inv;
    fp[tc + 32] = 1.f + e1 * inv;
}

// ---------------------------------------------------------------------------
// Kernel 3 (R4-proven): one block per (b, d). Row processed in 4 chunks of
// 1024 elements, double-buffered smem; each chunk drains via three 4 KB
// cp.async.bulk stores. Dynamic smem: 24 KB. Oversubscription (8192 CTAs)
// provides the latency hiding.
// ---------------------------------------------------------------------------
#define SMEM_MAIN_BYTES (2 * 3 * 1024 * 4)

__global__ __launch_bounds__(256) void main_kernel(
    const float* __restrict__ x, float* __restrict__ out)
{
    __shared__ float lev[352];
    extern __shared__ float smb[];   // [2][3][1024]

    int b = blockIdx.y;
    int d = blockIdx.x;
    int tid = threadIdx.x;

    if (tid < 64) lev[tid] = x[((size_t)(b * BD + d)) * 64 + tid];
    __syncthreads();
    const int offA[7] = {0, 64, 127, 188, 245, 294, 327};
#pragma unroll
    for (int l = 1; l < 7; l++) {
        int cnt = 65 - (1 << l);
        int half = 1 << (l - 1);
        if (tid < cnt)
            lev[offA[l] + tid] = fmaxf(lev[offA[l - 1] + tid],
                                       lev[offA[l - 1] + tid + half]);
        __syncthreads();
    }

    const size_t mapsz = (size_t)BB * BD * 4096;
    const int4*   tblv = (const int4*)g_tbl.v;
    const float4* facv = (const float4*)(d_factor + (size_t)b * 4096);
    float* maskp = out + 3 * mapsz + (size_t)b * 4096;
    float* gBase = out + ((size_t)(b * BD + d)) * 4096;

#pragma unroll
    for (int c = 0; c < 4; c++) {
        float* buf = smb + (c & 1) * 3072;
        if (c >= 2) {
            if (tid == 0)
                asm volatile("cp.async.bulk.wait_group.read 1;" ::: "memory");
            __syncthreads();
        }

        int q = c * 256 + tid;
        int4 t4 = tblv[q];
        int i  = q >> 4;
        int j0 = (q & 15) << 2;
        float4* pB = (float4*)buf + tid;
        float4* pL = (float4*)buf + 256 + tid;
        float4* pC = (float4*)buf + 512 + tid;

        if ((t4.x & t4.y & t4.z & t4.w) < 0) {
            float4 z = make_float4(0.f, 0.f, 0.f, 0.f);
            *pB = z; *pL = z; *pC = z;
            if (d == 0) __stcs((float4*)maskp + q, z);
        } else {
            float4 f4 = facv[q];
            float fs[4] = {f4.x, f4.y, f4.z, f4.w};
            int   ts[4] = {t4.x, t4.y, t4.z, t4.w};
            float xi = lev[i];
            float bo[4], lc[4], co[4], mk[4];
#pragma unroll
            for (int cc = 0; cc < 4; cc++) {
                int t = ts[cc];
                if (t < 0) { bo[cc] = 0.f; lc[cc] = 0.f; co[cc] = 0.f; mk[cc] = 0.f; }
                else {
                    int j = j0 + cc;
                    float xj = lev[j];
                    float xk = lev[(i + j) >> 1];
                    float f  = fs[cc];
                    bo[cc] = (xi + xj) * 0.5f * f;
                    lc[cc] = (xi + xj + 0.5f * xk) * (1.f / 2.5f) * f;
                    co[cc] = fmaxf(lev[t & 1023], lev[(t >> 10) & 1023]) * f;
                    mk[cc] = 1.f;
                }
            }
            *pB = make_float4(bo[0], bo[1], bo[2], bo[3]);
            *pL = make_float4(lc[0], lc[1], lc[2], lc[3]);
            *pC = make_float4(co[0], co[1], co[2], co[3]);
            if (d == 0) __stcs((float4*)maskp + q,
                               make_float4(mk[0], mk[1], mk[2], mk[3]));
        }
        __syncthreads();

        if (tid == 0) {
            uint32_t s0;
            asm("{ .reg .u64 t; cvta.to.shared.u64 t, %1; cvt.u32.u64 %0, t; }"
                : "=r"(s0) : "l"(buf));
            asm volatile("fence.proxy.async.shared::cta;" ::: "memory");
            asm volatile("cp.async.bulk.global.shared::cta.bulk_group [%0], [%1], %2;"
                         :: "l"(gBase + c * 1024), "r"(s0), "r"(4096) : "memory");
            asm volatile("cp.async.bulk.global.shared::cta.bulk_group [%0], [%1], %2;"
                         :: "l"(gBase + mapsz + c * 1024), "r"(s0 + 4096), "r"(4096) : "memory");
            asm volatile("cp.async.bulk.global.shared::cta.bulk_group [%0], [%1], %2;"
                         :: "l"(gBase + 2 * mapsz + c * 1024), "r"(s0 + 8192), "r"(4096) : "memory");
            asm volatile("cp.async.bulk.commit_group;" ::: "memory");
        }
    }

    if (tid == 0)
        asm volatile("cp.async.bulk.wait_group.read 0;" ::: "memory");
}

// ---------------------------------------------------------------------------
extern "C" void kernel_launch(void* const* d_in, const int* in_sizes, int n_in,
                              void* d_out, int out_size) {
    const float* x   = (const float*)d_in[0];
    const float* w_c = (const float*)d_in[1];
    const float* b_c = (const float*)d_in[2];
    const float* w_v = (const float*)d_in[3];
    const float* b_v = (const float*)d_in[4];
    float* out = (float*)d_out;

    gemm_kernel<<<dim3(8, 16, 2), 256>>>(x, w_v, w_c);
    attn_kernel<<<dim3(8, 16), 256>>>(b_v, b_c);
    main_kernel<<<dim3(512, 16), 256, SMEM_MAIN_BYTES>>>(x, out);
}